// round 15
// baseline (speedup 1.0000x reference)
#include <cuda_runtime.h>
#include <cuda_fp16.h>
#include <cstdint>

// Problem constants (fixed by the dataset):
//   N = 50000 nodes, C = 128 channels, E = 400000 edges,
//   T = 12 edge types, P = 16 (4x4 restriction map)
// Y layout per node: [half(src=0/dst=1)][t][p]  -> 2*12*16 = 384 cols
#define NMAX   50000
#define CDIM   128
#define NCOLS  384

// Scratch (allocation-free rule: __device__ globals)
__device__ __half g_Bh[NCOLS * CDIM];                // 96 KB, fp16 W^T: [n][k]
__device__ __half g_Yh[(size_t)NMAX * NCOLS];        // 38.4 MB, fp16 node partials

__device__ __forceinline__ uint32_t smem_u32(const void* p) {
    return (uint32_t)__cvta_generic_to_shared(p);
}
__device__ __forceinline__ void cp_async16(void* smem_dst, const void* gsrc) {
    asm volatile("cp.async.ca.shared.global [%0], [%1], 16;\n"
                 :: "r"(smem_u32(smem_dst)), "l"(gsrc));
}
#define CP_COMMIT() asm volatile("cp.async.commit_group;\n" ::)
#define CP_WAIT0()  asm volatile("cp.async.wait_group 0;\n" ::)

__device__ __forceinline__ void ldsm_x4(uint32_t& r0, uint32_t& r1,
                                        uint32_t& r2, uint32_t& r3,
                                        uint32_t addr) {
    asm volatile("ldmatrix.sync.aligned.m8n8.x4.shared.b16 {%0,%1,%2,%3}, [%4];"
                 : "=r"(r0), "=r"(r1), "=r"(r2), "=r"(r3) : "r"(addr));
}
__device__ __forceinline__ float fast_tanh(float x) {
    float y;
    asm("tanh.approx.f32 %0, %1;" : "=f"(y) : "f"(x));
    return y;
}

// ---------------------------------------------------------------------------
// Kernel 1: prep — coalesced read of W, scattered fp16 write to global.
// Thread i reads W[i]; i = ((t*256 + row)*16 + p), row = half*128 + c;
// writes g_Bh[n*128 + c] with n = half*192 + t*16 + p.
// ---------------------------------------------------------------------------
__global__ void prep_kernel(const float* __restrict__ W) {
    int i = blockIdx.x * blockDim.x + threadIdx.x;   // 0 .. 49151
    float w = W[i];
    int p   = i & 15;
    int row = (i >> 4) & 255;
    int t   = i >> 12;
    int half = row >> 7;
    int c    = row & 127;
    int n    = half * 192 + t * 16 + p;
    g_Bh[n * CDIM + c] = __float2half_rn(w);
}

// ---------------------------------------------------------------------------
// Kernel 2: Y[M,384] = fp16(X[M,128]) @ Bh^T, fp32 accumulate, fp16 out.
// Grid (ceil(M/128), 1): each CTA loads its A tile ONCE, loops 3 n-blocks.
// B tiles DOUBLE-BUFFERED: cp(B[nb+1]) issued right after the sync of nb,
// transferring under compute(nb); the wait at nb+1 returns immediately.
// Smem: A 34.8 KB + 2x B 34.8 KB = 104.4 KB; 2 CTAs/SM (208.9 <= 228 KB).
// 8 warps in 4(M) x 2(N); warp tile 32x64 via ldmatrix.x4 + mma.m16n8k16.
// SPAD=136 -> conflict-free LDSM phases.
// ---------------------------------------------------------------------------
#define SPAD      136
#define AS_ELEMS  (128 * SPAD)
#define BUF_BYTES (AS_ELEMS * 2)                     // 34816 B per tile buffer
#define GEMM_SMEM_BYTES (3 * BUF_BYTES)              // 104448 B (dynamic)

__global__ void __launch_bounds__(256, 2)
gemm_kernel(const float* __restrict__ X, int M) {
    extern __shared__ __half smem[];
    __half* As      = smem;                    // [128][SPAD]
    __half* Bbuf[2] = { smem + AS_ELEMS, smem + 2 * AS_ELEMS };

    const int m0  = blockIdx.x * 128;
    const int tid = threadIdx.x;

    // ---- Prefetch B[0] first (cp.async in flight under the A load) ----
    #pragma unroll
    for (int i = 0; i < 8; ++i) {
        int li = tid + i * 256;          // 0..2047
        int r  = li >> 4;                // n_local 0..127
        int c  = (li & 15) << 3;         // k chunk start (8 halves)
        cp_async16(Bbuf[0] + r * SPAD + c, g_Bh + (size_t)r * CDIM + c);
    }
    CP_COMMIT();

    // ---- A tile (once): LDG f32x4 -> cvt fp16 -> STS 8 B ----
    #pragma unroll
    for (int i = 0; i < 16; ++i) {
        int li = tid + i * 256;          // 0..4095
        int r  = li >> 5;                // m row 0..127
        int c  = (li & 31) << 2;         // k col (f32 granularity)
        float4 v = make_float4(0.f, 0.f, 0.f, 0.f);
        if (m0 + r < M)
            v = *reinterpret_cast<const float4*>(X + (size_t)(m0 + r) * CDIM + c);
        __half2 h0 = __floats2half2_rn(v.x, v.y);
        __half2 h1 = __floats2half2_rn(v.z, v.w);
        *reinterpret_cast<__half2*>(As + r * SPAD + c)     = h0;
        *reinterpret_cast<__half2*>(As + r * SPAD + c + 2) = h1;
    }

    const int warp = tid >> 5;
    const int lane = tid & 31;
    const int wm   = warp >> 1;   // 0..3
    const int wn   = warp & 1;    // 0..1
    const int mat  = lane >> 3;
    const int mrl  = lane & 7;

    // ldmatrix base addresses (k0 = 0); advance 32 B per k16 step.
    uint32_t a_addr[2];
    #pragma unroll
    for (int mt = 0; mt < 2; ++mt) {
        int row = wm * 32 + mt * 16 + (mat & 1) * 8 + mrl;
        int col = (mat >> 1) * 8;
        a_addr[mt] = smem_u32(As + row * SPAD + col);
    }
    uint32_t b_addr[4];     // relative to Bbuf[0]; buf1 = +BUF_BYTES
    #pragma unroll
    for (int g = 0; g < 4; ++g) {
        int row = wn * 64 + (2 * g + (mat >> 1)) * 8 + mrl;
        int col = (mat & 1) * 8;
        b_addr[g] = smem_u32(Bbuf[0] + row * SPAD + col);
    }

    const int grp   = lane >> 2;
    const int tig   = lane & 3;
    const int rbase = wm * 32 + grp;

    // ---- Loop over the 3 n-blocks; B double-buffered ----
    for (int nb = 0; nb < 3; ++nb) {
        CP_WAIT0();            // B[nb] landed (its group is the only one left)
        __syncthreads();       // B[nb] (+A on nb=0) visible; prior buf reads
                               // by ALL warps retired -> safe to overwrite
        if (nb + 1 < 3) {
            __half* nbuf = Bbuf[(nb + 1) & 1];
            const __half* src = g_Bh + (size_t)(nb + 1) * 128 * CDIM;
            #pragma unroll
            for (int i = 0; i < 8; ++i) {
                int li = tid + i * 256;
                int r  = li >> 4;
                int c  = (li & 15) << 3;
                cp_async16(nbuf + r * SPAD + c, src + (size_t)r * CDIM + c);
            }
            CP_COMMIT();       // transfers under compute(nb)
        }

        float acc[2][8][4];
        #pragma unroll
        for (int mt = 0; mt < 2; ++mt)
            #pragma unroll
            for (int nt = 0; nt < 8; ++nt)
                #pragma unroll
                for (int q = 0; q < 4; ++q)
                    acc[mt][nt][q] = 0.f;

        const uint32_t bo = (nb & 1) ? (uint32_t)BUF_BYTES : 0u;
        #pragma unroll
        for (int ks = 0; ks < CDIM / 16; ++ks) {  // 8 k16 steps
            const uint32_t koff = ks * 32;        // 16 halves = 32 B
            uint32_t a[2][4];
            #pragma unroll
            for (int mt = 0; mt < 2; ++mt)
                ldsm_x4(a[mt][0], a[mt][1], a[mt][2], a[mt][3],
                        a_addr[mt] + koff);
            uint32_t b[8][2];
            #pragma unroll
            for (int g = 0; g < 4; ++g)
                ldsm_x4(b[2 * g][0], b[2 * g][1],
                        b[2 * g + 1][0], b[2 * g + 1][1],
                        b_addr[g] + bo + koff);
            #pragma unroll
            for (int nt = 0; nt < 8; ++nt) {
                #pragma unroll
                for (int mt = 0; mt < 2; ++mt) {
                    asm volatile(
                        "mma.sync.aligned.m16n8k16.row.col.f32.f16.f16.f32 "
                        "{%0,%1,%2,%3}, {%4,%5,%6,%7}, {%8,%9}, {%0,%1,%2,%3};"
                        : "+f"(acc[mt][nt][0]), "+f"(acc[mt][nt][1]),
                          "+f"(acc[mt][nt][2]), "+f"(acc[mt][nt][3])
                        : "r"(a[mt][0]), "r"(a[mt][1]),
                          "r"(a[mt][2]), "r"(a[mt][3]),
                          "r"(b[nt][0]), "r"(b[nt][1]));
                }
            }
        }

        // Epilogue for this n-block: fp16 half2 stores
        const int n0 = nb * 128;
        #pragma unroll
        for (int mt = 0; mt < 2; ++mt) {
            int r0 = m0 + rbase + mt * 16;
            #pragma unroll
            for (int nt = 0; nt < 8; ++nt) {
                int cc = n0 + wn * 64 + nt * 8 + tig * 2;
                if (r0 < M) {
                    __half2 h = __floats2half2_rn(acc[mt][nt][0], acc[mt][nt][1]);
                    *reinterpret_cast<__half2*>(g_Yh + (size_t)r0 * NCOLS + cc) = h;
                }
                if (r0 + 8 < M) {
                    __half2 h = __floats2half2_rn(acc[mt][nt][2], acc[mt][nt][3]);
                    *reinterpret_cast<__half2*>(g_Yh + (size_t)(r0 + 8) * NCOLS + cc) = h;
                }
            }
        }
    }
}

// ---------------------------------------------------------------------------
// Kernel 3: per edge e, out[e,:16] = tanh(Ysrc[src,t,:] + Ydst[dst,t,:])
// ONE thread per edge: 3 index loads + 4 independent 16 B gathers (MLP,
// Y fp16 L2-resident), 16 MUFU tanh.approx, 64 B coalesced output.
// Index-dtype detect fused per block (edge_types in 0..11: if int64 LE,
// every odd int32 word is 0; false-positive prob on int32 data (1/12)^256).
// ---------------------------------------------------------------------------
__global__ void edge_kernel(const void* __restrict__ ei,
                            const void* __restrict__ et,
                            float* __restrict__ out, int E) {
    const int* etw = (const int*)et;
    int probe = etw[2 * threadIdx.x + 1];
    int idx64 = !__syncthreads_or(probe != 0);

    int e = blockIdx.x * blockDim.x + threadIdx.x;
    if (e >= E) return;

    int src, dst, t;
    if (idx64) {
        const long long* ei64 = (const long long*)ei;
        const long long* et64 = (const long long*)et;
        src = (int)ei64[e];
        dst = (int)ei64[(size_t)E + e];
        t   = (int)et64[e];
    } else {
        const int* ei32 = (const int*)ei;
        src = ei32[e];
        dst = ei32[(size_t)E + e];
        t   = etw[e];
    }

    const __half* pa = g_Yh + (size_t)src * NCOLS + t * 16;
    const __half* pb = g_Yh + (size_t)dst * NCOLS + 192 + t * 16;
    uint4 va0 = *reinterpret_cast<const uint4*>(pa);
    uint4 va1 = *reinterpret_cast<const uint4*>(pa + 8);
    uint4 vb0 = *reinterpret_cast<const uint4*>(pb);
    uint4 vb1 = *reinterpret_cast<const uint4*>(pb + 8);

    const __half2* a0 = reinterpret_cast<const __half2*>(&va0);
    const __half2* a1 = reinterpret_cast<const __half2*>(&va1);
    const __half2* b0 = reinterpret_cast<const __half2*>(&vb0);
    const __half2* b1 = reinterpret_cast<const __half2*>(&vb1);

    float r[16];
    #pragma unroll
    for (int i = 0; i < 4; ++i) {
        float2 fa = __half22float2(a0[i]);
        float2 fb = __half22float2(b0[i]);
        r[2 * i]     = fast_tanh(fa.x + fb.x);
        r[2 * i + 1] = fast_tanh(fa.y + fb.y);
        float2 ga = __half22float2(a1[i]);
        float2 gb = __half22float2(b1[i]);
        r[8 + 2 * i]     = fast_tanh(ga.x + gb.x);
        r[8 + 2 * i + 1] = fast_tanh(ga.y + gb.y);
    }
    float* o = out + (size_t)e * 16;
    *reinterpret_cast<float4*>(o)      = make_float4(r[0],  r[1],  r[2],  r[3]);
    *reinterpret_cast<float4*>(o + 4)  = make_float4(r[4],  r[5],  r[6],  r[7]);
    *reinterpret_cast<float4*>(o + 8)  = make_float4(r[8],  r[9],  r[10], r[11]);
    *reinterpret_cast<float4*>(o + 12) = make_float4(r[12], r[13], r[14], r[15]);
}

// ---------------------------------------------------------------------------
extern "C" void kernel_launch(void* const* d_in, const int* in_sizes, int n_in,
                              void* d_out, int out_size) {
    const float* x  = (const float*)d_in[0];      // [N,128] f32
    const void*  ei = d_in[1];                    // [2,E] int32 or int64
    const void*  et = d_in[2];                    // [E]   int32 or int64
    const float* W  = (const float*)d_in[3];      // [12,256,16] f32

    const int N = in_sizes[0] / CDIM;
    const int E = in_sizes[2];

    // Opt-in >48 KB dynamic smem (immediate host attr set; capture-legal,
    // unconditional -> deterministic).
    cudaFuncSetAttribute(gemm_kernel,
                         cudaFuncAttributeMaxDynamicSharedMemorySize,
                         GEMM_SMEM_BYTES);

    // 1) Weight rearrange/transpose to fp16
    prep_kernel<<<192, 256>>>(W);

    // 2) Dense node-side GEMM: A loaded once, 3 n-blocks, B double-buffered
    dim3 grid((N + 127) / 128, 1);
    gemm_kernel<<<grid, 256, GEMM_SMEM_BYTES>>>(x, N);

    // 3) Edge gather + add + tanh, 1 thread/edge
    edge_kernel<<<(E + 255) / 256, 256>>>(ei, et, (float*)d_out, E);
}

// round 16
// speedup vs baseline: 1.1294x; 1.1294x over previous
#include <cuda_runtime.h>
#include <cuda_fp16.h>
#include <cstdint>

// Problem constants (fixed by the dataset):
//   N = 50000 nodes, C = 128 channels, E = 400000 edges,
//   T = 12 edge types, P = 16 (4x4 restriction map)
// Y layout per node: [half(src=0/dst=1)][t][p]  -> 2*12*16 = 384 cols
#define NMAX   50000
#define CDIM   128
#define NCOLS  384

// Scratch (allocation-free rule: __device__ globals)
__device__ __half g_Bh[NCOLS * CDIM];                // 96 KB, fp16 W^T: [n][k]
__device__ __half g_Yh[(size_t)NMAX * NCOLS];        // 38.4 MB, fp16 node partials

__device__ __forceinline__ uint32_t smem_u32(const void* p) {
    return (uint32_t)__cvta_generic_to_shared(p);
}
__device__ __forceinline__ void cp_async16(void* smem_dst, const void* gsrc) {
    asm volatile("cp.async.ca.shared.global [%0], [%1], 16;\n"
                 :: "r"(smem_u32(smem_dst)), "l"(gsrc));
}
#define CP_COMMIT() asm volatile("cp.async.commit_group;\n" ::)
#define CP_WAIT0()  asm volatile("cp.async.wait_group 0;\n" ::)

__device__ __forceinline__ void ldsm_x4(uint32_t& r0, uint32_t& r1,
                                        uint32_t& r2, uint32_t& r3,
                                        uint32_t addr) {
    asm volatile("ldmatrix.sync.aligned.m8n8.x4.shared.b16 {%0,%1,%2,%3}, [%4];"
                 : "=r"(r0), "=r"(r1), "=r"(r2), "=r"(r3) : "r"(addr));
}
__device__ __forceinline__ float fast_tanh(float x) {
    float y;
    asm("tanh.approx.f32 %0, %1;" : "=f"(y) : "f"(x));
    return y;
}

// ---------------------------------------------------------------------------
// Kernel 1: prep — coalesced float4 read of W, scattered fp16 writes.
// Thread handles floats j..j+3; j = ((t*256 + row)*16 + p), row = half*128+c;
// dest n = half*192 + t*16 + p (p..p+3 consecutive within one k column).
// ---------------------------------------------------------------------------
__global__ void prep_kernel(const float* __restrict__ W) {
    int j = (blockIdx.x * blockDim.x + threadIdx.x) * 4;   // 0 .. 49148
    float4 v = *reinterpret_cast<const float4*>(W + j);
    int p   = j & 15;
    int row = (j >> 4) & 255;
    int t   = j >> 12;
    int half = row >> 7;
    int c    = row & 127;
    int n    = half * 192 + t * 16 + p;
    g_Bh[(n + 0) * CDIM + c] = __float2half_rn(v.x);
    g_Bh[(n + 1) * CDIM + c] = __float2half_rn(v.y);
    g_Bh[(n + 2) * CDIM + c] = __float2half_rn(v.z);
    g_Bh[(n + 3) * CDIM + c] = __float2half_rn(v.w);
}

// ---------------------------------------------------------------------------
// Kernel 2 (R14 verbatim — best measured): Y = fp16(X) @ Bh^T, fp32 acc.
// Grid (ceil(M/128), 1): A tile loaded ONCE, 3 n-blocks looped in-CTA.
// 8 warps in 4(M) x 2(N); warp tile 32x64 via ldmatrix.x4 + mma.m16n8k16.
// SPAD=136 -> conflict-free LDSM phases. 69.6 KB smem, 2 CTA/SM.
// ---------------------------------------------------------------------------
#define SPAD      136
#define AS_ELEMS  (128 * SPAD)
#define GEMM_SMEM_BYTES (2 * AS_ELEMS * 2)   // 69632 B (dynamic, opt-in)

__global__ void __launch_bounds__(256, 2)
gemm_kernel(const float* __restrict__ X, int M) {
    extern __shared__ __half smem[];
    __half* As = smem;              // [128][SPAD]  rows = m, cols = k
    __half* Bs = smem + AS_ELEMS;   // [128][SPAD]  rows = n_local, cols = k

    const int m0  = blockIdx.x * 128;
    const int tid = threadIdx.x;

    // ---- A tile (once): LDG f32x4 -> cvt fp16 -> STS 8 B ----
    #pragma unroll
    for (int i = 0; i < 16; ++i) {
        int li = tid + i * 256;          // 0..4095
        int r  = li >> 5;                // m row 0..127
        int c  = (li & 31) << 2;         // k col (f32 granularity)
        float4 v = make_float4(0.f, 0.f, 0.f, 0.f);
        if (m0 + r < M)
            v = *reinterpret_cast<const float4*>(X + (size_t)(m0 + r) * CDIM + c);
        __half2 h0 = __floats2half2_rn(v.x, v.y);
        __half2 h1 = __floats2half2_rn(v.z, v.w);
        *reinterpret_cast<__half2*>(As + r * SPAD + c)     = h0;
        *reinterpret_cast<__half2*>(As + r * SPAD + c + 2) = h1;
    }

    const int warp = tid >> 5;
    const int lane = tid & 31;
    const int wm   = warp >> 1;   // 0..3
    const int wn   = warp & 1;    // 0..1
    const int mat  = lane >> 3;
    const int mrl  = lane & 7;

    uint32_t a_addr[2];
    #pragma unroll
    for (int mt = 0; mt < 2; ++mt) {
        int row = wm * 32 + mt * 16 + (mat & 1) * 8 + mrl;
        int col = (mat >> 1) * 8;
        a_addr[mt] = smem_u32(As + row * SPAD + col);
    }
    uint32_t b_addr[4];
    #pragma unroll
    for (int g = 0; g < 4; ++g) {
        int row = wn * 64 + (2 * g + (mat >> 1)) * 8 + mrl;
        int col = (mat & 1) * 8;
        b_addr[g] = smem_u32(Bs + row * SPAD + col);
    }

    const int grp   = lane >> 2;
    const int tig   = lane & 3;
    const int rbase = wm * 32 + grp;

    // ---- Loop over the 3 n-blocks, reusing A and acc registers ----
    for (int nb = 0; nb < 3; ++nb) {
        const int n0 = nb * 128;

        // B tile: straight fp16 row copy via cp.async (L2-resident source)
        #pragma unroll
        for (int i = 0; i < 8; ++i) {
            int li = tid + i * 256;          // 0..2047
            int r  = li >> 4;                // n_local 0..127
            int c  = (li & 15) << 3;         // k chunk start (8 halves)
            cp_async16(Bs + r * SPAD + c, g_Bh + (size_t)(n0 + r) * CDIM + c);
        }
        CP_COMMIT();
        CP_WAIT0();
        __syncthreads();                     // B (and, on nb=0, A) visible

        float acc[2][8][4];
        #pragma unroll
        for (int mt = 0; mt < 2; ++mt)
            #pragma unroll
            for (int nt = 0; nt < 8; ++nt)
                #pragma unroll
                for (int q = 0; q < 4; ++q)
                    acc[mt][nt][q] = 0.f;

        #pragma unroll
        for (int ks = 0; ks < CDIM / 16; ++ks) {  // 8 k16 steps
            const uint32_t koff = ks * 32;        // 16 halves = 32 B
            uint32_t a[2][4];
            #pragma unroll
            for (int mt = 0; mt < 2; ++mt)
                ldsm_x4(a[mt][0], a[mt][1], a[mt][2], a[mt][3],
                        a_addr[mt] + koff);
            uint32_t b[8][2];
            #pragma unroll
            for (int g = 0; g < 4; ++g)
                ldsm_x4(b[2 * g][0], b[2 * g][1],
                        b[2 * g + 1][0], b[2 * g + 1][1], b_addr[g] + koff);
            #pragma unroll
            for (int nt = 0; nt < 8; ++nt) {
                #pragma unroll
                for (int mt = 0; mt < 2; ++mt) {
                    asm volatile(
                        "mma.sync.aligned.m16n8k16.row.col.f32.f16.f16.f32 "
                        "{%0,%1,%2,%3}, {%4,%5,%6,%7}, {%8,%9}, {%0,%1,%2,%3};"
                        : "+f"(acc[mt][nt][0]), "+f"(acc[mt][nt][1]),
                          "+f"(acc[mt][nt][2]), "+f"(acc[mt][nt][3])
                        : "r"(a[mt][0]), "r"(a[mt][1]),
                          "r"(a[mt][2]), "r"(a[mt][3]),
                          "r"(b[nt][0]), "r"(b[nt][1]));
                }
            }
        }

        // Epilogue for this n-block: fp16 half2 stores
        #pragma unroll
        for (int mt = 0; mt < 2; ++mt) {
            int r0 = m0 + rbase + mt * 16;
            #pragma unroll
            for (int nt = 0; nt < 8; ++nt) {
                int cc = n0 + wn * 64 + nt * 8 + tig * 2;
                if (r0 < M) {
                    __half2 h = __floats2half2_rn(acc[mt][nt][0], acc[mt][nt][1]);
                    *reinterpret_cast<__half2*>(g_Yh + (size_t)r0 * NCOLS + cc) = h;
                }
                if (r0 + 8 < M) {
                    __half2 h = __floats2half2_rn(acc[mt][nt][2], acc[mt][nt][3]);
                    *reinterpret_cast<__half2*>(g_Yh + (size_t)(r0 + 8) * NCOLS + cc) = h;
                }
            }
        }
        __syncthreads();   // all warps done reading Bs before next cp.async
    }
}

// ---------------------------------------------------------------------------
// Kernel 3: TWO threads per edge (measured-best gather shape: 16 distinct
// lines per warp gather instruction instead of 32 -> half the L1 wavefront
// pressure, which R13 ncu showed as the binding pipe at 45.8%).
// Each thread: 3 index loads + 2 independent 16 B gathers + 8 MUFU tanh +
// 32 B coalesced output. Index-dtype detect fused per block (edge_types in
// 0..11: if int64 LE, every odd int32 word is 0; FP prob (1/12)^256).
// ---------------------------------------------------------------------------
__global__ void edge_kernel(const void* __restrict__ ei,
                            const void* __restrict__ et,
                            float* __restrict__ out, int E) {
    const int* etw = (const int*)et;
    int probe = etw[2 * threadIdx.x + 1];
    int idx64 = !__syncthreads_or(probe != 0);

    int gid = blockIdx.x * blockDim.x + threadIdx.x;
    int e = gid >> 1;
    if (e >= E) return;
    int h = (gid & 1) << 3;   // 0 or 8 (element offset within the 16)

    int src, dst, t;
    if (idx64) {
        const long long* ei64 = (const long long*)ei;
        const long long* et64 = (const long long*)et;
        src = (int)ei64[e];
        dst = (int)ei64[(size_t)E + e];
        t   = (int)et64[e];
    } else {
        const int* ei32 = (const int*)ei;
        src = ei32[e];
        dst = ei32[(size_t)E + e];
        t   = etw[e];
    }

    const uint4 va = *reinterpret_cast<const uint4*>(
        g_Yh + (size_t)src * NCOLS + t * 16 + h);
    const uint4 vb = *reinterpret_cast<const uint4*>(
        g_Yh + (size_t)dst * NCOLS + 192 + t * 16 + h);
    const __half2* pa = reinterpret_cast<const __half2*>(&va);
    const __half2* pb = reinterpret_cast<const __half2*>(&vb);

    float r[8];
    #pragma unroll
    for (int i = 0; i < 4; ++i) {
        float2 fa = __half22float2(pa[i]);
        float2 fb = __half22float2(pb[i]);
        r[2 * i]     = fast_tanh(fa.x + fb.x);
        r[2 * i + 1] = fast_tanh(fa.y + fb.y);
    }
    float* o = out + (size_t)e * 16 + h;
    *reinterpret_cast<float4*>(o)     = make_float4(r[0], r[1], r[2], r[3]);
    *reinterpret_cast<float4*>(o + 4) = make_float4(r[4], r[5], r[6], r[7]);
}

// ---------------------------------------------------------------------------
extern "C" void kernel_launch(void* const* d_in, const int* in_sizes, int n_in,
                              void* d_out, int out_size) {
    const float* x  = (const float*)d_in[0];      // [N,128] f32
    const void*  ei = d_in[1];                    // [2,E] int32 or int64
    const void*  et = d_in[2];                    // [E]   int32 or int64
    const float* W  = (const float*)d_in[3];      // [12,256,16] f32

    const int N = in_sizes[0] / CDIM;
    const int E = in_sizes[2];

    // Opt-in >48 KB dynamic smem (immediate host attr set; capture-legal,
    // unconditional -> deterministic).
    cudaFuncSetAttribute(gemm_kernel,
                         cudaFuncAttributeMaxDynamicSharedMemorySize,
                         GEMM_SMEM_BYTES);

    // 1) Weight rearrange/transpose to fp16 (float4 reads)
    prep_kernel<<<48, 256>>>(W);

    // 2) Dense node-side GEMM: A loaded once, 3 n-blocks looped in-CTA
    dim3 grid((N + 127) / 128, 1);
    gemm_kernel<<<grid, 256, GEMM_SMEM_BYTES>>>(x, N);

    // 3) Edge gather + add + tanh, 2 threads/edge
    int threads = E * 2;
    edge_kernel<<<(threads + 255) / 256, 256>>>(ei, et, (float*)d_out, E);
}